// round 13
// baseline (speedup 1.0000x reference)
#include <cuda_runtime.h>

#define NROWS 14400   // 16 * 900
#define NC    91
#define MT    1600
#define TN    10      // rows per block: grid=1440 -> 1.95 waves at 5 blocks/SM
#define EPSF  1e-8f

__global__ __launch_bounds__(256, 5) void cost_kernel(
    const float* __restrict__ pred_logits, // [NROWS, NC]
    const float* __restrict__ pred_boxes,  // [NROWS, 4] cxcywh
    const int*   __restrict__ tgt_ids,     // [MT] int32
    const float* __restrict__ tgt_bbox,    // [MT, 4] cxcywh
    float*       __restrict__ out)         // [NROWS, MT]
{
    __shared__ float4 s_tb[MT];        // tgt (cx, cy, w/2, h/2)
    __shared__ int    s_tid[MT];       // tgt class ids
    __shared__ float  s_cc[TN * NC];   // focal cost slice, +1.0 baked in
    __shared__ float4 s_pb[TN];        // pred (cx, cy, w/2, h/2)

    const int tid = threadIdx.x;
    const int n0  = blockIdx.x * TN;

    for (int i = tid; i < MT; i += 256) {
        float4 tb = ((const float4*)tgt_bbox)[i];
        s_tb[i] = make_float4(tb.x, tb.y, 0.5f * tb.z, 0.5f * tb.w);
        int id  = tgt_ids[i];
        s_tid[i] = (id < 0) ? 0 : (id >= NC ? NC - 1 : id);
    }
    // Fused focal-cost prep (fast-math). Stores cc + 1.0.
    for (int i = tid; i < TN * NC; i += 256) {
        float x = pred_logits[n0 * NC + i];
        float e = __expf(-x);
        float p = __fdividef(1.0f, 1.0f + e);
        float omp = 1.0f - p;
        float lp = __logf(p + EPSF);
        float lo = __logf(omp + EPSF);
        s_cc[i] = fmaf(-0.25f * omp * omp, lp, fmaf(0.75f * p * p, lo, 1.0f));
    }
    if (tid < TN) {
        float4 pb = ((const float4*)pred_boxes)[n0 + tid];
        s_pb[tid] = make_float4(pb.x, pb.y, 0.5f * pb.z, 0.5f * pb.w);
    }
    __syncthreads();

    // Each thread owns groups of 4 consecutive target columns (float4 stores).
    for (int g = tid; g < MT / 4; g += 256) {
        const int m0 = g * 4;

        // Per-column cache: cx, cy, hw, hh, full tgt area, cc gather pointer
        float tcx[4], tcy[4], htw[4], hth[4], ta4[4];
        const float* cj[4];
#pragma unroll
        for (int j = 0; j < 4; j++) {
            float4 tb = s_tb[m0 + j];
            tcx[j] = tb.x;
            tcy[j] = tb.y;
            htw[j] = tb.z;
            hth[j] = tb.w;
            ta4[j] = 4.0f * tb.z * tb.w;   // full tgt area
            cj[j]  = s_cc + s_tid[m0 + j]; // row access: cj[j][r*NC] (imm offset)
        }

#pragma unroll
        for (int r = 0; r < TN; r++) {
            float4 pbr = s_pb[r];
            float pcx = pbr.x, pcy = pbr.y;
            float hpw = pbr.z, hph = pbr.w;
            float pa4 = 4.0f * hpw * hph;  // full pred area

            float4 res;
            float* rp = &res.x;
#pragma unroll
            for (int j = 0; j < 4; j++) {
                // Shared |diff| terms (abs folds into consumers as operand modifier)
                float dx = fabsf(pcx - tcx[j]);
                float dy = fabsf(pcy - tcy[j]);
                float sx = fabsf(hpw - htw[j]);   // 0.5|pw - tw|
                float sy = fabsf(hph - hth[j]);
                // L1: dx + dy + 2(sx + sy)
                float cb = fmaf(2.0f, sx + sy, dx + dy);
                // Interval identity (halves cancel): overlap_w = (hpw+htw) - max(dx, sx)
                float ax = hpw + htw[j];
                float ay = hph + hth[j];
                float bx = fmaxf(dx, sx);
                float by = fmaxf(dy, sy);
                float iw = fmaxf(ax - bx, 0.0f);  // full intersection width
                float ih = fmaxf(ay - by, 0.0f);
                float inter = iw * ih;                    // full intersection area
                float uni   = (pa4 + ta4[j]) - inter;     // full union
                float ea    = (ax + bx) * (ay + by);      // full enclosing area
                // One reciprocal; fold both ratios into a single chain:
                //   iou + q = (inter*ea + uni*uni) * rcp(uni*ea)
                float denom = uni * ea;
                float rd;
                asm("rcp.approx.f32 %0, %1;" : "=f"(rd) : "f"(denom));
                float geo = fmaf(inter, ea, uni * uni) * rd;
                // cost = cb + (cc+1) - (iou + q)   (the +1 is baked into s_cc)
                float cc1 = cj[j][r * NC];                // LDS [reg + imm]
                rp[j] = (cb + cc1) - geo;
            }
            ((float4*)out)[((size_t)(n0 + r) * MT + m0) >> 2] = res;
        }
    }
}

extern "C" void kernel_launch(void* const* d_in, const int* in_sizes, int n_in,
                              void* d_out, int out_size) {
    const float* pred_logits = (const float*)d_in[0];  // [16,900,91]
    const float* pred_boxes  = (const float*)d_in[1];  // [16,900,4]
    const int*   tgt_ids     = (const int*)d_in[2];    // [1600] int32
    const float* tgt_bbox    = (const float*)d_in[3];  // [1600,4]
    float*       out         = (float*)d_out;          // [16,900,1600]

    cost_kernel<<<NROWS / TN, 256>>>(pred_logits, pred_boxes, tgt_ids, tgt_bbox, out);
}

// round 16
// speedup vs baseline: 1.1068x; 1.1068x over previous
#include <cuda_runtime.h>

#define NROWS 14400   // 16 * 900
#define NC    91
#define MT    1600
#define TN    12      // rows per block: grid=1200 -> 2.03 waves at 4 blocks/SM
#define EPSF  1e-8f

__global__ __launch_bounds__(256, 4) void cost_kernel(
    const float* __restrict__ pred_logits, // [NROWS, NC]
    const float* __restrict__ pred_boxes,  // [NROWS, 4] cxcywh
    const int*   __restrict__ tgt_ids,     // [MT] int32
    const float* __restrict__ tgt_bbox,    // [MT, 4] cxcywh
    float*       __restrict__ out)         // [NROWS, MT]
{
    __shared__ float4 s_tb[MT];        // tgt (cx, cy, w/2, h/2)
    __shared__ int    s_tid[MT];       // tgt class ids
    __shared__ float  s_cc[TN * NC];   // focal cost slice, +1.0 baked in
    __shared__ float4 s_pb[TN];        // pred (cx, cy, w/2, h/2)

    const int tid = threadIdx.x;
    const int n0  = blockIdx.x * TN;

    for (int i = tid; i < MT; i += 256) {
        float4 tb = ((const float4*)tgt_bbox)[i];
        s_tb[i] = make_float4(tb.x, tb.y, 0.5f * tb.z, 0.5f * tb.w);
        int id  = tgt_ids[i];
        s_tid[i] = (id < 0) ? 0 : (id >= NC ? NC - 1 : id);
    }
    // Fused focal-cost prep (fast-math). Stores cc + 1.0.
    for (int i = tid; i < TN * NC; i += 256) {
        float x = pred_logits[n0 * NC + i];
        float e = __expf(-x);
        float p = __fdividef(1.0f, 1.0f + e);
        float omp = 1.0f - p;
        float lp = __logf(p + EPSF);
        float lo = __logf(omp + EPSF);
        s_cc[i] = fmaf(-0.25f * omp * omp, lp, fmaf(0.75f * p * p, lo, 1.0f));
    }
    if (tid < TN) {
        float4 pb = ((const float4*)pred_boxes)[n0 + tid];
        s_pb[tid] = make_float4(pb.x, pb.y, 0.5f * pb.z, 0.5f * pb.w);
    }
    __syncthreads();

    // Each thread owns groups of 4 consecutive target columns.
    for (int g = tid; g < MT / 4; g += 256) {
        const int m0 = g * 4;

        // Per-column cache: cx, cy, hw, hh, full tgt area, cc gather pointer
        float tcx[4], tcy[4], htw[4], hth[4], ta4[4];
        const float* cj[4];
#pragma unroll
        for (int j = 0; j < 4; j++) {
            float4 tb = s_tb[m0 + j];
            tcx[j] = tb.x;
            tcy[j] = tb.y;
            htw[j] = tb.z;
            hth[j] = tb.w;
            ta4[j] = 4.0f * tb.z * tb.w;   // full tgt area
            cj[j]  = s_cc + s_tid[m0 + j]; // row access: cj[j][r*NC] (imm offset)
        }

#pragma unroll
        for (int r = 0; r < TN; r++) {
            float4 pbr = s_pb[r];
            float pcx = pbr.x, pcy = pbr.y;
            float hpw = pbr.z, hph = pbr.w;
            float pa4 = 4.0f * hpw * hph;  // full pred area

            float v[4];
#pragma unroll
            for (int j = 0; j < 4; j++) {
                // Shared |diff| terms (abs folds into consumers as operand modifier)
                float dx = fabsf(pcx - tcx[j]);
                float dy = fabsf(pcy - tcy[j]);
                float sx = fabsf(hpw - htw[j]);   // 0.5|pw - tw|
                float sy = fabsf(hph - hth[j]);
                // L1: dx + dy + 2(sx + sy)
                float cb = fmaf(2.0f, sx + sy, dx + dy);
                // Interval identity (halves cancel): overlap_w = (hpw+htw) - max(dx, sx)
                float ax = hpw + htw[j];
                float ay = hph + hth[j];
                float bx = fmaxf(dx, sx);
                float by = fmaxf(dy, sy);
                // ax < 1 and ax-bx <= ax, so max(x,0) == saturate(x): free .SAT modifier
                float iw = __saturatef(ax - bx);  // full intersection width
                float ih = __saturatef(ay - by);
                float inter = iw * ih;                    // full intersection area
                float uni   = (pa4 + ta4[j]) - inter;     // full union
                float ea    = (ax + bx) * (ay + by);      // full enclosing area
                // One reciprocal; both ratios in one numerator:
                //   iou + q = (inter*ea + uni*uni) * rcp(uni*ea)
                float denom = uni * ea;
                float rd;
                asm("rcp.approx.f32 %0, %1;" : "=f"(rd) : "f"(denom));
                float num = fmaf(inter, ea, uni * uni);
                // cost = (cb + cc+1) - num*rd  -> single FFMA with negated operand
                float cc1 = cj[j][r * NC];                // LDS [reg + imm]
                v[j] = fmaf(-num, rd, cb + cc1);
            }
            float* dst = out + (size_t)(n0 + r) * MT + m0;
            asm volatile("st.global.cs.v4.f32 [%0], {%1, %2, %3, %4};"
                         :: "l"(dst), "f"(v[0]), "f"(v[1]), "f"(v[2]), "f"(v[3])
                         : "memory");
        }
    }
}

extern "C" void kernel_launch(void* const* d_in, const int* in_sizes, int n_in,
                              void* d_out, int out_size) {
    const float* pred_logits = (const float*)d_in[0];  // [16,900,91]
    const float* pred_boxes  = (const float*)d_in[1];  // [16,900,4]
    const int*   tgt_ids     = (const int*)d_in[2];    // [1600] int32
    const float* tgt_bbox    = (const float*)d_in[3];  // [1600,4]
    float*       out         = (float*)d_out;          // [16,900,1600]

    cost_kernel<<<NROWS / TN, 256>>>(pred_logits, pred_boxes, tgt_ids, tgt_bbox, out);
}